// round 1
// baseline (speedup 1.0000x reference)
#include <cuda_runtime.h>
#include <math.h>

// Problem constants
#define NB 4
#define NC 128
#define NP 128
#define ND 128
#define NH 8
#define NR 16
#define NG 512
#define NROW (NB * NC * NP)            // 65536
#define NELEM ((size_t)NROW * ND)      // 8388608
#define PAD 129

// -------------------- scratch (static __device__, no allocs) --------------------
__device__ float g_qzn[NELEM];
__device__ float g_xacc[NELEM];
__device__ float g_tu[NELEM];
__device__ float g_tv[NELEM];
__device__ float g_cu[NELEM];
__device__ float g_cv[NELEM];

// =====================================================================
// K1: qzn = LN(qz); xacc = 0.5*(qz + unary)
// one warp per row of 128
// =====================================================================
__global__ __launch_bounds__(256) void k_ln_init(
    const float* __restrict__ qz, const float* __restrict__ unary,
    const float* __restrict__ gamma, const float* __restrict__ beta) {
    int row = blockIdx.x * 8 + (threadIdx.x >> 5);
    int lane = threadIdx.x & 31;
    size_t base = (size_t)row * 128 + lane * 4;
    float4 v = *(const float4*)(qz + base);
    float s = v.x + v.y + v.z + v.w;
    float ss = v.x * v.x + v.y * v.y + v.z * v.z + v.w * v.w;
#pragma unroll
    for (int o = 16; o > 0; o >>= 1) {
        s += __shfl_xor_sync(0xffffffffu, s, o);
        ss += __shfl_xor_sync(0xffffffffu, ss, o);
    }
    float m = s * (1.0f / 128.0f);
    float var = ss * (1.0f / 128.0f) - m * m;
    float inv = rsqrtf(var + 1e-5f);
    float4 u = *(const float4*)(unary + base);
    float4 g4 = *(const float4*)(gamma + lane * 4);
    float4 b4 = *(const float4*)(beta + lane * 4);
    float4 qn, xa;
    qn.x = (v.x - m) * inv * g4.x + b4.x;
    qn.y = (v.y - m) * inv * g4.y + b4.y;
    qn.z = (v.z - m) * inv * g4.z + b4.z;
    qn.w = (v.w - m) * inv * g4.w + b4.w;
    xa.x = 0.5f * (v.x + u.x);
    xa.y = 0.5f * (v.y + u.y);
    xa.z = 0.5f * (v.z + u.z);
    xa.w = 0.5f * (v.w + u.w);
    *(float4*)(g_qzn + base) = qn;
    *(float4*)(g_xacc + base) = xa;
}

// =====================================================================
// K2: batched linears: O[row, o] = sum_d qzn[row, d] * W[b][o, d]
// grid = (row_tiles=1024, 4 weights). 64 rows per block, 256 threads.
// =====================================================================
__global__ __launch_bounds__(256) void k_gemm4(
    const float* __restrict__ w0, const float* __restrict__ w1,
    const float* __restrict__ w2, const float* __restrict__ w3) {
    extern __shared__ float sm[];
    float* Xs = sm;              // 64 x PAD
    float* Ws = sm + 64 * PAD;   // 128 x PAD
    int tid = threadIdx.x;
    int row0 = blockIdx.x * 64;
    int b = row0 >> 14;  // / 16384
    int which = blockIdx.y;
    const float* W = (which == 0 ? w0 : which == 1 ? w1 : which == 2 ? w2 : w3)
                     + (size_t)b * 16384;
    float* O = (which == 0 ? g_tu : which == 1 ? g_tv : which == 2 ? g_cu : g_cv);

    for (int i = tid; i < 64 * 128; i += 256) {
        int r = i >> 7, c = i & 127;
        Xs[r * PAD + c] = g_qzn[(size_t)(row0 + r) * 128 + c];
    }
    for (int i = tid; i < 128 * 128; i += 256) {
        int r = i >> 7, c = i & 127;
        Ws[r * PAD + c] = W[i];
    }
    __syncthreads();

    int tx = tid & 31, ty = tid >> 5;
    float acc[8][4] = {};
    for (int k = 0; k < 128; k++) {
        float bb[4], a[8];
#pragma unroll
        for (int j = 0; j < 4; j++) bb[j] = Ws[(tx + 32 * j) * PAD + k];
#pragma unroll
        for (int i = 0; i < 8; i++) a[i] = Xs[(ty * 8 + i) * PAD + k];
#pragma unroll
        for (int i = 0; i < 8; i++)
#pragma unroll
            for (int j = 0; j < 4; j++) acc[i][j] = fmaf(a[i], bb[j], acc[i][j]);
    }
#pragma unroll
    for (int i = 0; i < 8; i++)
#pragma unroll
        for (int j = 0; j < 4; j++)
            O[(size_t)(row0 + ty * 8 + i) * 128 + tx + 32 * j] = acc[i][j];
}

// =====================================================================
// Shared attention core: A[p][q] = (1/H) sum_h softmax_q( 0.25 * U_h[p]·V_h[q] )
// U, V: [128][PAD] smem; A: [128][PAD] smem (pre-zeroed). warp w owns rows
// [16w, 16w+16).
// =====================================================================
__device__ __forceinline__ void attn_avg(const float* __restrict__ U,
                                         const float* __restrict__ V,
                                         float* __restrict__ A,
                                         int lane, int w) {
    for (int h = 0; h < 8; h++) {
        int ho = h * 16;
        for (int pi = 0; pi < 16; pi++) {
            int p = w * 16 + pi;
            float s0 = 0, s1 = 0, s2 = 0, s3 = 0;
            const float* up = U + p * PAD + ho;
#pragma unroll
            for (int r = 0; r < 16; r++) {
                float uv = up[r];
                s0 = fmaf(uv, V[(lane) * PAD + ho + r], s0);
                s1 = fmaf(uv, V[(lane + 32) * PAD + ho + r], s1);
                s2 = fmaf(uv, V[(lane + 64) * PAD + ho + r], s2);
                s3 = fmaf(uv, V[(lane + 96) * PAD + ho + r], s3);
            }
            s0 *= 0.25f; s1 *= 0.25f; s2 *= 0.25f; s3 *= 0.25f;
            float mx = fmaxf(fmaxf(s0, s1), fmaxf(s2, s3));
#pragma unroll
            for (int o = 16; o > 0; o >>= 1) mx = fmaxf(mx, __shfl_xor_sync(0xffffffffu, mx, o));
            float e0 = expf(s0 - mx), e1 = expf(s1 - mx);
            float e2 = expf(s2 - mx), e3 = expf(s3 - mx);
            float sum = e0 + e1 + e2 + e3;
#pragma unroll
            for (int o = 16; o > 0; o >>= 1) sum += __shfl_xor_sync(0xffffffffu, sum, o);
            float inv = 1.0f / (sum * 8.0f);
            float* ap = A + p * PAD + lane;
            ap[0]  += e0 * inv;
            ap[32] += e1 * inv;
            ap[64] += e2 * inv;
            ap[96] += e3 * inv;
        }
    }
}

// =====================================================================
// K3: time attention. block = (b,c). m_t = A @ qzn[b,c]; xacc += 0.5*m_t
// =====================================================================
__global__ __launch_bounds__(256) void k_time_attn() {
    extern __shared__ float sm[];
    float* U = sm;
    float* V = sm + 128 * PAD;
    float* A = sm + 2 * 128 * PAD;
    int tid = threadIdx.x, lane = tid & 31, w = tid >> 5;
    size_t base = (size_t)blockIdx.x * 16384;

    for (int i = tid; i < 16384; i += 256) {
        int r = i >> 7, c = i & 127;
        U[r * PAD + c] = g_tu[base + i];
        V[r * PAD + c] = g_tv[base + i];
    }
    for (int i = tid; i < 128 * PAD; i += 256) A[i] = 0.0f;
    __syncthreads();

    attn_avg(U, V, A, lane, w);
    __syncthreads();

    // reuse U for qzn tile
    for (int i = tid; i < 16384; i += 256) {
        int r = i >> 7, c = i & 127;
        U[r * PAD + c] = g_qzn[base + i];
    }
    __syncthreads();

    float acc[16][4] = {};
    for (int q = 0; q < 128; q++) {
        float bb[4];
#pragma unroll
        for (int j = 0; j < 4; j++) bb[j] = U[q * PAD + lane + 32 * j];
#pragma unroll
        for (int i = 0; i < 16; i++) {
            float a = A[(w * 16 + i) * PAD + q];
#pragma unroll
            for (int j = 0; j < 4; j++) acc[i][j] = fmaf(a, bb[j], acc[i][j]);
        }
    }
#pragma unroll
    for (int i = 0; i < 16; i++)
#pragma unroll
        for (int j = 0; j < 4; j++)
            g_xacc[base + (size_t)(w * 16 + i) * 128 + lane + 32 * j] += 0.5f * acc[i][j];
}

// =====================================================================
// K4: channel attention. block = (b,p). xacc[b,c,p,d] += 0.5*A[c][d]*qzn[b,c,p,d]
// =====================================================================
__global__ __launch_bounds__(256) void k_chan_attn() {
    extern __shared__ float sm[];
    float* U = sm;
    float* V = sm + 128 * PAD;
    float* A = sm + 2 * 128 * PAD;
    int tid = threadIdx.x, lane = tid & 31, w = tid >> 5;
    int bp = blockIdx.x;
    int b = bp >> 7, p = bp & 127;
    size_t base = (size_t)b * 2097152 + (size_t)p * 128;

    for (int i = tid; i < 16384; i += 256) {
        int c = i >> 7, d = i & 127;
        size_t g = base + (size_t)c * 16384 + d;
        U[c * PAD + d] = g_cu[g];
        V[c * PAD + d] = g_cv[g];
    }
    for (int i = tid; i < 128 * PAD; i += 256) A[i] = 0.0f;
    __syncthreads();

    attn_avg(U, V, A, lane, w);
    __syncthreads();

    for (int i = tid; i < 16384; i += 256) {
        int c = i >> 7, d = i & 127;
        size_t g = base + (size_t)c * 16384 + d;
        g_xacc[g] += 0.5f * A[c * PAD + d] * g_qzn[g];
    }
}

// =====================================================================
// K5: topic branch. block = 64 rows. m_g = (sum_g relu(s)·T[g]) / max(sum relu, eps)
// single pass over G in 4 chunks of 128.
// =====================================================================
__global__ __launch_bounds__(256) void k_topic(const float* __restrict__ topic) {
    extern __shared__ float sm[];
    float* T = sm;                 // 128 x PAD
    float* Q = sm + 128 * PAD;     // 64 x PAD
    float* S = sm + 192 * PAD;     // 64 x PAD
    float* rs = sm + 256 * PAD;    // 64 row sums
    int tid = threadIdx.x, tx = tid & 31, ty = tid >> 5;
    int row0 = blockIdx.x * 64;
    int b = row0 >> 14;
    const float* Tb = topic + (size_t)b * NG * 128;

    for (int i = tid; i < 64 * 128; i += 256) {
        int r = i >> 7, c = i & 127;
        Q[r * PAD + c] = g_qzn[(size_t)(row0 + r) * 128 + c];
    }
    if (tid < 64) rs[tid] = 0.0f;
    float macc[8][4] = {};
    __syncthreads();

    for (int gc = 0; gc < 4; gc++) {
        for (int i = tid; i < 16384; i += 256) {
            int g = i >> 7, d = i & 127;
            T[g * PAD + d] = Tb[(size_t)(gc * 128 + g) * 128 + d];
        }
        __syncthreads();

        float sacc[8][4] = {};
        for (int k = 0; k < 128; k++) {
            float bb[4], a[8];
#pragma unroll
            for (int j = 0; j < 4; j++) bb[j] = T[(tx + 32 * j) * PAD + k];
#pragma unroll
            for (int i = 0; i < 8; i++) a[i] = Q[(ty * 8 + i) * PAD + k];
#pragma unroll
            for (int i = 0; i < 8; i++)
#pragma unroll
                for (int j = 0; j < 4; j++) sacc[i][j] = fmaf(a[i], bb[j], sacc[i][j]);
        }
#pragma unroll
        for (int i = 0; i < 8; i++) {
            float part = 0.0f;
#pragma unroll
            for (int j = 0; j < 4; j++) {
                float v = fmaxf(sacc[i][j], 0.0f);
                S[(ty * 8 + i) * PAD + tx + 32 * j] = v;
                part += v;
            }
#pragma unroll
            for (int o = 16; o > 0; o >>= 1) part += __shfl_xor_sync(0xffffffffu, part, o);
            if (tx == 0) rs[ty * 8 + i] += part;
        }
        __syncthreads();

        for (int g = 0; g < 128; g++) {
            float bb[4], a[8];
#pragma unroll
            for (int j = 0; j < 4; j++) bb[j] = T[g * PAD + tx + 32 * j];
#pragma unroll
            for (int i = 0; i < 8; i++) a[i] = S[(ty * 8 + i) * PAD + g];
#pragma unroll
            for (int i = 0; i < 8; i++)
#pragma unroll
                for (int j = 0; j < 4; j++) macc[i][j] = fmaf(a[i], bb[j], macc[i][j]);
        }
        __syncthreads();
    }
#pragma unroll
    for (int i = 0; i < 8; i++) {
        float dn = fmaxf(rs[ty * 8 + i], 1e-6f);
        float idn = 0.5f / dn;
#pragma unroll
        for (int j = 0; j < 4; j++)
            g_xacc[(size_t)(row0 + ty * 8 + i) * 128 + tx + 32 * j] += macc[i][j] * idn;
    }
}

// =====================================================================
// K6: out = x + gelu(LN(x) @ w1^T + b1) @ w2^T + b2.  64 rows per block.
// =====================================================================
__global__ __launch_bounds__(256) void k_mlp(
    const float* __restrict__ gamma, const float* __restrict__ beta,
    const float* __restrict__ w1, const float* __restrict__ b1,
    const float* __restrict__ w2, const float* __restrict__ b2,
    float* __restrict__ out) {
    extern __shared__ float sm[];
    float* W1 = sm;                 // 128 x PAD
    float* W2 = sm + 128 * PAD;     // 128 x PAD
    float* Hs = sm + 256 * PAD;     // 64 x PAD
    float* Ts = sm + 320 * PAD;     // 64 x PAD
    int tid = threadIdx.x, tx = tid & 31, ty = tid >> 5;
    int row0 = blockIdx.x * 64;

    for (int i = tid; i < 16384; i += 256) {
        int r = i >> 7, c = i & 127;
        W1[r * PAD + c] = w1[i];
        W2[r * PAD + c] = w2[i];
    }
    // LN: warp per row, 8 iterations
    float4 g4 = *(const float4*)(gamma + tx * 4);
    float4 b4 = *(const float4*)(beta + tx * 4);
    for (int it = 0; it < 8; it++) {
        int r = ty * 8 + it;
        size_t base = (size_t)(row0 + r) * 128 + tx * 4;
        float4 v = *(const float4*)(g_xacc + base);
        float s = v.x + v.y + v.z + v.w;
        float ss = v.x * v.x + v.y * v.y + v.z * v.z + v.w * v.w;
#pragma unroll
        for (int o = 16; o > 0; o >>= 1) {
            s += __shfl_xor_sync(0xffffffffu, s, o);
            ss += __shfl_xor_sync(0xffffffffu, ss, o);
        }
        float m = s * (1.0f / 128.0f);
        float var = ss * (1.0f / 128.0f) - m * m;
        float inv = rsqrtf(var + 1e-5f);
        float* hp = Hs + r * PAD + tx * 4;
        hp[0] = (v.x - m) * inv * g4.x + b4.x;
        hp[1] = (v.y - m) * inv * g4.y + b4.y;
        hp[2] = (v.z - m) * inv * g4.z + b4.z;
        hp[3] = (v.w - m) * inv * g4.w + b4.w;
    }
    __syncthreads();

    float bs1[4], bs2[4];
#pragma unroll
    for (int j = 0; j < 4; j++) { bs1[j] = b1[tx + 32 * j]; bs2[j] = b2[tx + 32 * j]; }

    float acc[8][4] = {};
    for (int k = 0; k < 128; k++) {
        float bb[4], a[8];
#pragma unroll
        for (int j = 0; j < 4; j++) bb[j] = W1[(tx + 32 * j) * PAD + k];
#pragma unroll
        for (int i = 0; i < 8; i++) a[i] = Hs[(ty * 8 + i) * PAD + k];
#pragma unroll
        for (int i = 0; i < 8; i++)
#pragma unroll
            for (int j = 0; j < 4; j++) acc[i][j] = fmaf(a[i], bb[j], acc[i][j]);
    }
#pragma unroll
    for (int i = 0; i < 8; i++)
#pragma unroll
        for (int j = 0; j < 4; j++) {
            float v = acc[i][j] + bs1[j];
            float g = 0.5f * v * (1.0f + erff(v * 0.70710678118654752f));
            Ts[(ty * 8 + i) * PAD + tx + 32 * j] = g;
        }
    __syncthreads();

    float acc2[8][4] = {};
    for (int o = 0; o < 128; o++) {
        float bb[4], a[8];
#pragma unroll
        for (int j = 0; j < 4; j++) bb[j] = W2[(tx + 32 * j) * PAD + o];
#pragma unroll
        for (int i = 0; i < 8; i++) a[i] = Ts[(ty * 8 + i) * PAD + o];
#pragma unroll
        for (int i = 0; i < 8; i++)
#pragma unroll
            for (int j = 0; j < 4; j++) acc2[i][j] = fmaf(a[i], bb[j], acc2[i][j]);
    }
#pragma unroll
    for (int i = 0; i < 8; i++)
#pragma unroll
        for (int j = 0; j < 4; j++) {
            size_t g = (size_t)(row0 + ty * 8 + i) * 128 + tx + 32 * j;
            out[g] = g_xacc[g] + acc2[i][j] + bs2[j];
        }
}

// =====================================================================
// launch
// =====================================================================
extern "C" void kernel_launch(void* const* d_in, const int* in_sizes, int n_in,
                              void* d_out, int out_size) {
    const float* qz    = (const float*)d_in[0];
    const float* unary = (const float*)d_in[1];
    const float* tuw   = (const float*)d_in[2];
    const float* tvw   = (const float*)d_in[3];
    const float* cuw   = (const float*)d_in[4];
    const float* cvw   = (const float*)d_in[5];
    const float* topic = (const float*)d_in[6];
    const float* gamma = (const float*)d_in[7];
    const float* beta  = (const float*)d_in[8];
    const float* w1    = (const float*)d_in[9];
    const float* b1    = (const float*)d_in[10];
    const float* w2    = (const float*)d_in[11];
    const float* b2    = (const float*)d_in[12];
    float* out = (float*)d_out;

    const int SM2 = (64 + 128) * PAD * 4;              // 99072
    const int SM3 = 3 * 128 * PAD * 4;                 // 198144
    const int SM5 = 256 * PAD * 4 + 64 * 4;            // 132352
    const int SM6 = 384 * PAD * 4;                     // 198144

    cudaFuncSetAttribute(k_gemm4, cudaFuncAttributeMaxDynamicSharedMemorySize, SM2);
    cudaFuncSetAttribute(k_time_attn, cudaFuncAttributeMaxDynamicSharedMemorySize, SM3);
    cudaFuncSetAttribute(k_chan_attn, cudaFuncAttributeMaxDynamicSharedMemorySize, SM3);
    cudaFuncSetAttribute(k_topic, cudaFuncAttributeMaxDynamicSharedMemorySize, SM5);
    cudaFuncSetAttribute(k_mlp, cudaFuncAttributeMaxDynamicSharedMemorySize, SM6);

    k_ln_init<<<NROW / 8, 256>>>(qz, unary, gamma, beta);
    k_gemm4<<<dim3(NROW / 64, 4), 256, SM2>>>(tuw, tvw, cuw, cvw);
    k_time_attn<<<NB * NC, 256, SM3>>>();
    k_chan_attn<<<NB * NP, 256, SM3>>>();
    k_topic<<<NROW / 64, 256, SM5>>>(topic);
    k_mlp<<<NROW / 64, 256, SM6>>>(gamma, beta, w1, b1, w2, b2, out);
}

// round 2
// speedup vs baseline: 1.5320x; 1.5320x over previous
#include <cuda_runtime.h>
#include <math.h>

// Problem constants
#define NB 4
#define NC 128
#define NP 128
#define ND 128
#define NG 512
#define NROW (NB * NC * NP)            // 65536
#define NELEM ((size_t)NROW * ND)      // 8388608

typedef unsigned long long u64;

// -------------------- scratch (static __device__, no allocs) --------------------
__device__ float g_qzn[NELEM];
__device__ float g_xacc[NELEM];
__device__ float g_tu[NELEM];
__device__ float g_tv[NELEM];
__device__ float g_cu[NELEM];
__device__ float g_cv[NELEM];

// -------------------- packed f32x2 helpers --------------------
__device__ __forceinline__ u64 pk2(float lo, float hi) {
    u64 r; asm("mov.b64 %0, {%1,%2};" : "=l"(r) : "f"(lo), "f"(hi)); return r;
}
__device__ __forceinline__ float2 up2(u64 v) {
    float2 f; asm("mov.b64 {%0,%1}, %2;" : "=f"(f.x), "=f"(f.y) : "l"(v)); return f;
}
__device__ __forceinline__ void fma2(u64 &d, u64 a, u64 b) {
    asm("fma.rn.f32x2 %0, %1, %2, %0;" : "+l"(d) : "l"(a), "l"(b));
}

// =====================================================================
// K1: qzn = LN(qz); xacc = 0.5*(qz + unary).  one warp per row of 128.
// =====================================================================
__global__ __launch_bounds__(256) void k_ln_init(
    const float* __restrict__ qz, const float* __restrict__ unary,
    const float* __restrict__ gamma, const float* __restrict__ beta) {
    int row = blockIdx.x * 8 + (threadIdx.x >> 5);
    int lane = threadIdx.x & 31;
    size_t base = (size_t)row * 128 + lane * 4;
    float4 v = *(const float4*)(qz + base);
    float s = v.x + v.y + v.z + v.w;
    float ss = v.x * v.x + v.y * v.y + v.z * v.z + v.w * v.w;
#pragma unroll
    for (int o = 16; o > 0; o >>= 1) {
        s += __shfl_xor_sync(0xffffffffu, s, o);
        ss += __shfl_xor_sync(0xffffffffu, ss, o);
    }
    float m = s * (1.0f / 128.0f);
    float var = ss * (1.0f / 128.0f) - m * m;
    float inv = rsqrtf(var + 1e-5f);
    float4 u = *(const float4*)(unary + base);
    float4 g4 = *(const float4*)(gamma + lane * 4);
    float4 b4 = *(const float4*)(beta + lane * 4);
    float4 qn, xa;
    qn.x = (v.x - m) * inv * g4.x + b4.x;
    qn.y = (v.y - m) * inv * g4.y + b4.y;
    qn.z = (v.z - m) * inv * g4.z + b4.z;
    qn.w = (v.w - m) * inv * g4.w + b4.w;
    xa.x = 0.5f * (v.x + u.x);
    xa.y = 0.5f * (v.y + u.y);
    xa.z = 0.5f * (v.z + u.z);
    xa.w = 0.5f * (v.w + u.w);
    *(float4*)(g_qzn + base) = qn;
    *(float4*)(g_xacc + base) = xa;
}

// =====================================================================
// K2: 4 batched linears. 128 rows/block, 512 threads, grid (512, 4).
// Xt: k-major [128k][130r], Ws: natural [128o][129k].
// =====================================================================
#define P130 130
#define P129 129
#define P66  66

__global__ __launch_bounds__(512) void k_gemm4(
    const float* __restrict__ w0, const float* __restrict__ w1,
    const float* __restrict__ w2, const float* __restrict__ w3) {
    extern __shared__ float sm[];
    float* Xt = sm;                 // 128 x 130
    float* Ws = sm + 128 * P130;    // 128 x 129
    int tid = threadIdx.x, lane = tid & 31, w = tid >> 5;
    int row0 = blockIdx.x * 128;
    int b = row0 >> 14;
    int which = blockIdx.y;
    const float* W = (which == 0 ? w0 : which == 1 ? w1 : which == 2 ? w2 : w3)
                     + (size_t)b * 16384;
    float* O = (which == 0 ? g_tu : which == 1 ? g_tv : which == 2 ? g_cu : g_cv);

    for (int i = tid; i < 16384; i += 512) {
        int r = i >> 7, k = i & 127;
        Xt[k * P130 + r] = g_qzn[(size_t)(row0 + r) * 128 + k];
        Ws[r * P129 + k] = W[i];
    }
    __syncthreads();

    u64 acc[4][4];
#pragma unroll
    for (int i = 0; i < 4; i++)
#pragma unroll
        for (int j = 0; j < 4; j++) acc[i][j] = 0ull;

    int rbase = w * 8;
#pragma unroll 4
    for (int k = 0; k < 128; k++) {
        u64 a2[4], bb[4];
#pragma unroll
        for (int i = 0; i < 4; i++)
            a2[i] = *(const u64*)(Xt + k * P130 + rbase + 2 * i);
#pragma unroll
        for (int j = 0; j < 4; j++) {
            float bv = Ws[(lane + 32 * j) * P129 + k];
            bb[j] = pk2(bv, bv);
        }
#pragma unroll
        for (int i = 0; i < 4; i++)
#pragma unroll
            for (int j = 0; j < 4; j++) fma2(acc[i][j], a2[i], bb[j]);
    }
#pragma unroll
    for (int i = 0; i < 4; i++)
#pragma unroll
        for (int j = 0; j < 4; j++) {
            float2 v = up2(acc[i][j]);
            size_t g = (size_t)(row0 + rbase + 2 * i) * 128 + lane + 32 * j;
            O[g] = v.x;
            O[g + 128] = v.y;
        }
}

// =====================================================================
// attention score + head-avg softmax core.
// Ut: [128d][130p] (pre-scaled by 0.25), V: [128q][129d].
// Produces At[q*130 + p] = (1/16)*sum_h softmax_q(...)  (0.5 * head-mean)
// warp w owns rows p = w*8 .. w*8+7 (4 pairs).
// =====================================================================
__device__ __forceinline__ void attn_core(const float* __restrict__ Ut,
                                          const float* __restrict__ V,
                                          float* __restrict__ At,
                                          int lane, int w) {
    u64 accP[4][4];
#pragma unroll
    for (int i = 0; i < 4; i++)
#pragma unroll
        for (int j = 0; j < 4; j++) accP[i][j] = 0ull;
    int rbase = w * 8;

    for (int h = 0; h < 8; h++) {
        int ho = h * 16;
        u64 s2[4][4];
#pragma unroll
        for (int i = 0; i < 4; i++)
#pragma unroll
            for (int j = 0; j < 4; j++) s2[i][j] = 0ull;
#pragma unroll
        for (int r = 0; r < 16; r++) {
            int k = ho + r;
            u64 a2[4], bb[4];
#pragma unroll
            for (int i = 0; i < 4; i++)
                a2[i] = *(const u64*)(Ut + k * P130 + rbase + 2 * i);
#pragma unroll
            for (int j = 0; j < 4; j++) {
                float bv = V[(lane + 32 * j) * P129 + k];
                bb[j] = pk2(bv, bv);
            }
#pragma unroll
            for (int i = 0; i < 4; i++)
#pragma unroll
                for (int j = 0; j < 4; j++) fma2(s2[i][j], a2[i], bb[j]);
        }
        // softmax per row-pair, accumulate into accP
#pragma unroll
        for (int i = 0; i < 4; i++) {
            float2 sv[4];
#pragma unroll
            for (int j = 0; j < 4; j++) sv[j] = up2(s2[i][j]);
            float mx0 = fmaxf(fmaxf(sv[0].x, sv[1].x), fmaxf(sv[2].x, sv[3].x));
            float mx1 = fmaxf(fmaxf(sv[0].y, sv[1].y), fmaxf(sv[2].y, sv[3].y));
#pragma unroll
            for (int o = 16; o > 0; o >>= 1) {
                mx0 = fmaxf(mx0, __shfl_xor_sync(0xffffffffu, mx0, o));
                mx1 = fmaxf(mx1, __shfl_xor_sync(0xffffffffu, mx1, o));
            }
            float e0[4], e1[4];
            float su0 = 0.f, su1 = 0.f;
#pragma unroll
            for (int j = 0; j < 4; j++) {
                e0[j] = __expf(sv[j].x - mx0);
                e1[j] = __expf(sv[j].y - mx1);
                su0 += e0[j]; su1 += e1[j];
            }
#pragma unroll
            for (int o = 16; o > 0; o >>= 1) {
                su0 += __shfl_xor_sync(0xffffffffu, su0, o);
                su1 += __shfl_xor_sync(0xffffffffu, su1, o);
            }
            float inv0 = __fdividef(1.0f, su0 * 16.0f);
            float inv1 = __fdividef(1.0f, su1 * 16.0f);
            u64 ip = pk2(inv0, inv1);
#pragma unroll
            for (int j = 0; j < 4; j++) fma2(accP[i][j], pk2(e0[j], e1[j]), ip);
        }
    }
    // write At[q][p-pair]
#pragma unroll
    for (int i = 0; i < 4; i++)
#pragma unroll
        for (int j = 0; j < 4; j++)
            *(u64*)(At + (lane + 32 * j) * P130 + rbase + 2 * i) = accP[i][j];
}

// =====================================================================
// K3: time attention. block = (b,c). xacc += At^T @ qzn (factor folded)
// =====================================================================
__global__ __launch_bounds__(512) void k_time_attn() {
    extern __shared__ float sm[];
    float* Ut = sm;                              // 128 x 130
    float* V = sm + 128 * P130;                  // 128 x 129
    float* At = sm + 128 * P130 + 128 * P129;    // 128 x 130
    int tid = threadIdx.x, lane = tid & 31, w = tid >> 5;
    size_t base = (size_t)blockIdx.x * 16384;

    for (int i = tid; i < 16384; i += 512) {
        int p = i >> 7, d = i & 127;
        Ut[d * P130 + p] = 0.25f * g_tu[base + i];
        V[p * P129 + d] = g_tv[base + i];
    }
    __syncthreads();

    attn_core(Ut, V, At, lane, w);
    __syncthreads();

    for (int i = tid; i < 16384; i += 512) {
        int p = i >> 7, d = i & 127;
        V[p * P129 + d] = g_qzn[base + i];
    }
    __syncthreads();

    int rbase = w * 8;
    u64 m[4][4];
#pragma unroll
    for (int i = 0; i < 4; i++)
#pragma unroll
        for (int j = 0; j < 4; j++) m[i][j] = 0ull;
#pragma unroll 4
    for (int q = 0; q < 128; q++) {
        u64 a2[4], bb[4];
#pragma unroll
        for (int i = 0; i < 4; i++)
            a2[i] = *(const u64*)(At + q * P130 + rbase + 2 * i);
#pragma unroll
        for (int j = 0; j < 4; j++) {
            float bv = V[q * P129 + lane + 32 * j];
            bb[j] = pk2(bv, bv);
        }
#pragma unroll
        for (int i = 0; i < 4; i++)
#pragma unroll
            for (int j = 0; j < 4; j++) fma2(m[i][j], a2[i], bb[j]);
    }
#pragma unroll
    for (int i = 0; i < 4; i++)
#pragma unroll
        for (int j = 0; j < 4; j++) {
            float2 v = up2(m[i][j]);
            size_t g = base + (size_t)(rbase + 2 * i) * 128 + lane + 32 * j;
            g_xacc[g] += v.x;
            g_xacc[g + 128] += v.y;
        }
}

// =====================================================================
// K4: channel attention. block = (b,p). xacc[b,c,p,d] += At[d][c]*qzn
// =====================================================================
__global__ __launch_bounds__(512) void k_chan_attn() {
    extern __shared__ float sm[];
    float* Ut = sm;
    float* V = sm + 128 * P130;
    float* At = sm + 128 * P130 + 128 * P129;
    int tid = threadIdx.x, lane = tid & 31, w = tid >> 5;
    int bp = blockIdx.x;
    int b = bp >> 7, p = bp & 127;
    size_t base = (size_t)b * 2097152 + (size_t)p * 128;

    for (int i = tid; i < 16384; i += 512) {
        int c = i >> 7, d = i & 127;
        size_t g = base + (size_t)c * 16384 + d;
        Ut[d * P130 + c] = 0.25f * g_cu[g];
        V[c * P129 + d] = g_cv[g];
    }
    __syncthreads();

    attn_core(Ut, V, At, lane, w);
    __syncthreads();

    for (int i = tid; i < 16384; i += 512) {
        int c = i >> 7, d = i & 127;
        size_t g = base + (size_t)c * 16384 + d;
        g_xacc[g] += At[d * P130 + c] * g_qzn[g];
    }
}

// =====================================================================
// K5: topic branch. 64 rows/block, 512 threads, 1024 blocks.
// =====================================================================
__global__ __launch_bounds__(512) void k_topic(const float* __restrict__ topic) {
    extern __shared__ float sm[];
    float* Qt = sm;                          // [128k][66r]
    float* Tn = sm + 128 * P66;              // [128g][129d]
    float* St = Tn + 128 * P129;             // [128g][66r]
    float* rs = St + 128 * P66;              // [64]
    int tid = threadIdx.x, lane = tid & 31, w = tid >> 5;
    int row0 = blockIdx.x * 64;
    int b = row0 >> 14;
    const float* Tb = topic + (size_t)b * NG * 128;
    int rbase = w * 4;

    for (int i = tid; i < 64 * 128; i += 512) {
        int r = i >> 7, k = i & 127;
        Qt[k * P66 + r] = g_qzn[(size_t)(row0 + r) * 128 + k];
    }
    if (tid < 64) rs[tid] = 0.0f;

    u64 macc[2][4];
#pragma unroll
    for (int i = 0; i < 2; i++)
#pragma unroll
        for (int j = 0; j < 4; j++) macc[i][j] = 0ull;

    for (int gc = 0; gc < 4; gc++) {
        __syncthreads();
        for (int i = tid; i < 16384; i += 512) {
            int g = i >> 7, d = i & 127;
            Tn[g * P129 + d] = Tb[(size_t)(gc * 128 + g) * 128 + d];
        }
        __syncthreads();

        // gemm1: S[r][g] = Q[r][:] . T[g][:]
        u64 s2[2][4];
#pragma unroll
        for (int i = 0; i < 2; i++)
#pragma unroll
            for (int j = 0; j < 4; j++) s2[i][j] = 0ull;
#pragma unroll 4
        for (int k = 0; k < 128; k++) {
            u64 a2[2], bb[4];
#pragma unroll
            for (int i = 0; i < 2; i++)
                a2[i] = *(const u64*)(Qt + k * P66 + rbase + 2 * i);
#pragma unroll
            for (int j = 0; j < 4; j++) {
                float bv = Tn[(lane + 32 * j) * P129 + k];
                bb[j] = pk2(bv, bv);
            }
#pragma unroll
            for (int i = 0; i < 2; i++)
#pragma unroll
                for (int j = 0; j < 4; j++) fma2(s2[i][j], a2[i], bb[j]);
        }
        // relu + row sums + store St
#pragma unroll
        for (int i = 0; i < 2; i++) {
            float2 v[4];
            float su0 = 0.f, su1 = 0.f;
#pragma unroll
            for (int j = 0; j < 4; j++) {
                v[j] = up2(s2[i][j]);
                v[j].x = fmaxf(v[j].x, 0.0f);
                v[j].y = fmaxf(v[j].y, 0.0f);
                su0 += v[j].x; su1 += v[j].y;
            }
#pragma unroll
            for (int o = 16; o > 0; o >>= 1) {
                su0 += __shfl_xor_sync(0xffffffffu, su0, o);
                su1 += __shfl_xor_sync(0xffffffffu, su1, o);
            }
            if (lane == 0) {
                rs[rbase + 2 * i] += su0;
                rs[rbase + 2 * i + 1] += su1;
            }
#pragma unroll
            for (int j = 0; j < 4; j++)
                *(u64*)(St + (lane + 32 * j) * P66 + rbase + 2 * i) = pk2(v[j].x, v[j].y);
        }
        __syncthreads();

        // gemm2: M[r][d] += S[r][g] * T[g][d]
#pragma unroll 4
        for (int g = 0; g < 128; g++) {
            u64 a2[2], bb[4];
#pragma unroll
            for (int i = 0; i < 2; i++)
                a2[i] = *(const u64*)(St + g * P66 + rbase + 2 * i);
#pragma unroll
            for (int j = 0; j < 4; j++) {
                float bv = Tn[g * P129 + lane + 32 * j];
                bb[j] = pk2(bv, bv);
            }
#pragma unroll
            for (int i = 0; i < 2; i++)
#pragma unroll
                for (int j = 0; j < 4; j++) fma2(macc[i][j], a2[i], bb[j]);
        }
    }
    __syncthreads();
#pragma unroll
    for (int i = 0; i < 2; i++) {
        float idn0 = 0.5f / fmaxf(rs[rbase + 2 * i], 1e-6f);
        float idn1 = 0.5f / fmaxf(rs[rbase + 2 * i + 1], 1e-6f);
#pragma unroll
        for (int j = 0; j < 4; j++) {
            float2 v = up2(macc[i][j]);
            size_t g = (size_t)(row0 + rbase + 2 * i) * 128 + lane + 32 * j;
            g_xacc[g] += v.x * idn0;
            g_xacc[g + 128] += v.y * idn1;
        }
    }
}

// =====================================================================
// K6: out = x + gelu(LN(x) @ w1^T + b1) @ w2^T + b2. 64 rows/block.
// =====================================================================
__global__ __launch_bounds__(512) void k_mlp(
    const float* __restrict__ gamma, const float* __restrict__ beta,
    const float* __restrict__ w1, const float* __restrict__ b1,
    const float* __restrict__ w2, const float* __restrict__ b2,
    float* __restrict__ out) {
    extern __shared__ float sm[];
    float* W1n = sm;                       // 128 x 129
    float* W2n = sm + 128 * P129;          // 128 x 129
    float* Ht = W2n + 128 * P129;          // [128d][66r]
    float* Tt = Ht + 128 * P66;            // [128o][66r]
    int tid = threadIdx.x, lane = tid & 31, w = tid >> 5;
    int row0 = blockIdx.x * 64;
    int rbase = w * 4;

    for (int i = tid; i < 16384; i += 512) {
        int r = i >> 7, c = i & 127;
        W1n[r * P129 + c] = w1[i];
        W2n[r * P129 + c] = w2[i];
    }
    // LN of xacc, write transposed into Ht
    float4 g4 = *(const float4*)(gamma + lane * 4);
    float4 b4 = *(const float4*)(beta + lane * 4);
#pragma unroll
    for (int it = 0; it < 4; it++) {
        int r = rbase + it;
        size_t gb = (size_t)(row0 + r) * 128 + lane * 4;
        float4 v = *(const float4*)(g_xacc + gb);
        float s = v.x + v.y + v.z + v.w;
        float ss = v.x * v.x + v.y * v.y + v.z * v.z + v.w * v.w;
#pragma unroll
        for (int o = 16; o > 0; o >>= 1) {
            s += __shfl_xor_sync(0xffffffffu, s, o);
            ss += __shfl_xor_sync(0xffffffffu, ss, o);
        }
        float m = s * (1.0f / 128.0f);
        float var = ss * (1.0f / 128.0f) - m * m;
        float inv = rsqrtf(var + 1e-5f);
        Ht[(lane * 4 + 0) * P66 + r] = (v.x - m) * inv * g4.x + b4.x;
        Ht[(lane * 4 + 1) * P66 + r] = (v.y - m) * inv * g4.y + b4.y;
        Ht[(lane * 4 + 2) * P66 + r] = (v.z - m) * inv * g4.z + b4.z;
        Ht[(lane * 4 + 3) * P66 + r] = (v.w - m) * inv * g4.w + b4.w;
    }
    __syncthreads();

    float bs1[4], bs2[4];
#pragma unroll
    for (int j = 0; j < 4; j++) {
        bs1[j] = b1[lane + 32 * j];
        bs2[j] = b2[lane + 32 * j];
    }

    // gemm1 + gelu -> Tt
    u64 acc[2][4];
#pragma unroll
    for (int i = 0; i < 2; i++)
#pragma unroll
        for (int j = 0; j < 4; j++) acc[i][j] = 0ull;
#pragma unroll 4
    for (int k = 0; k < 128; k++) {
        u64 a2[2], bb[4];
#pragma unroll
        for (int i = 0; i < 2; i++)
            a2[i] = *(const u64*)(Ht + k * P66 + rbase + 2 * i);
#pragma unroll
        for (int j = 0; j < 4; j++) {
            float bv = W1n[(lane + 32 * j) * P129 + k];
            bb[j] = pk2(bv, bv);
        }
#pragma unroll
        for (int i = 0; i < 2; i++)
#pragma unroll
            for (int j = 0; j < 4; j++) fma2(acc[i][j], a2[i], bb[j]);
    }
#pragma unroll
    for (int i = 0; i < 2; i++)
#pragma unroll
        for (int j = 0; j < 4; j++) {
            float2 v = up2(acc[i][j]);
            float x0 = v.x + bs1[j], x1 = v.y + bs1[j];
            float gl0 = 0.5f * x0 * (1.0f + erff(x0 * 0.70710678118654752f));
            float gl1 = 0.5f * x1 * (1.0f + erff(x1 * 0.70710678118654752f));
            *(u64*)(Tt + (lane + 32 * j) * P66 + rbase + 2 * i) = pk2(gl0, gl1);
        }
    __syncthreads();

    // gemm2 -> out
    u64 acc2[2][4];
#pragma unroll
    for (int i = 0; i < 2; i++)
#pragma unroll
        for (int j = 0; j < 4; j++) acc2[i][j] = 0ull;
#pragma unroll 4
    for (int o = 0; o < 128; o++) {
        u64 a2[2], bb[4];
#pragma unroll
        for (int i = 0; i < 2; i++)
            a2[i] = *(const u64*)(Tt + o * P66 + rbase + 2 * i);
#pragma unroll
        for (int j = 0; j < 4; j++) {
            float bv = W2n[(lane + 32 * j) * P129 + o];
            bb[j] = pk2(bv, bv);
        }
#pragma unroll
        for (int i = 0; i < 2; i++)
#pragma unroll
            for (int j = 0; j < 4; j++) fma2(acc2[i][j], a2[i], bb[j]);
    }
#pragma unroll
    for (int i = 0; i < 2; i++)
#pragma unroll
        for (int j = 0; j < 4; j++) {
            float2 v = up2(acc2[i][j]);
            size_t g = (size_t)(row0 + rbase + 2 * i) * 128 + lane + 32 * j;
            out[g] = g_xacc[g] + v.x + bs2[j];
            out[g + 128] = g_xacc[g + 128] + v.y + bs2[j];
        }
}

// =====================================================================
// launch
// =====================================================================
extern "C" void kernel_launch(void* const* d_in, const int* in_sizes, int n_in,
                              void* d_out, int out_size) {
    const float* qz    = (const float*)d_in[0];
    const float* unary = (const float*)d_in[1];
    const float* tuw   = (const float*)d_in[2];
    const float* tvw   = (const float*)d_in[3];
    const float* cuw   = (const float*)d_in[4];
    const float* cvw   = (const float*)d_in[5];
    const float* topic = (const float*)d_in[6];
    const float* gamma = (const float*)d_in[7];
    const float* beta  = (const float*)d_in[8];
    const float* w1    = (const float*)d_in[9];
    const float* b1    = (const float*)d_in[10];
    const float* w2    = (const float*)d_in[11];
    const float* b2    = (const float*)d_in[12];
    float* out = (float*)d_out;

    const int SM2 = (128 * P130 + 128 * P129) * 4;                 // 132608
    const int SMA = (128 * P130 * 2 + 128 * P129) * 4;             // 199168
    const int SM5 = (128 * P66 * 2 + 128 * P129 + 64) * 4;         // 133888
    const int SM6 = (128 * P129 * 2 + 128 * P66 * 2) * 4;          // 199680

    cudaFuncSetAttribute(k_gemm4, cudaFuncAttributeMaxDynamicSharedMemorySize, SM2);
    cudaFuncSetAttribute(k_time_attn, cudaFuncAttributeMaxDynamicSharedMemorySize, SMA);
    cudaFuncSetAttribute(k_chan_attn, cudaFuncAttributeMaxDynamicSharedMemorySize, SMA);
    cudaFuncSetAttribute(k_topic, cudaFuncAttributeMaxDynamicSharedMemorySize, SM5);
    cudaFuncSetAttribute(k_mlp, cudaFuncAttributeMaxDynamicSharedMemorySize, SM6);

    k_ln_init<<<NROW / 8, 256>>>(qz, unary, gamma, beta);
    k_gemm4<<<dim3(NROW / 128, 4), 512, SM2>>>(tuw, tvw, cuw, cvw);
    k_time_attn<<<NB * NC, 512, SMA>>>();
    k_chan_attn<<<NB * NP, 512, SMA>>>();
    k_topic<<<NROW / 64, 512, SM5>>>(topic);
    k_mlp<<<NROW / 64, 512, SM6>>>(gamma, beta, w1, b1, w2, b2, out);
}